// round 1
// baseline (speedup 1.0000x reference)
#include <cuda_runtime.h>

// out[b, oz, oy, ox] = in[b * 3137*768 + (1 + n*196 + g1*14 + g2)*768 + ch]
// where z = floor(oz*9/4), y = floor(oy*63/32), x = floor(ox*63/32),
//       n=z/9 c0=z%9, g1=y/9 c1=y%9, g2=x/9 c2=x%9,
//       ch = floor(float32(c0*81+c1*9+c2) * float32(768.0/729.0))   (bit-exact JAX path)

__global__ __launch_bounds__(256)
void FRAMES_VisionTransformer_28166395527587_kernel(const float* __restrict__ in,
                                                    float* __restrict__ out) {
    // One thread = 4 consecutive ox outputs. Total outputs 64*64*64*64 = 2^24.
    unsigned t = blockIdx.x * blockDim.x + threadIdx.x;   // 2^22 threads
    unsigned ox0 = (t & 15u) << 2;       // ox base (0..60 step 4)
    unsigned oy  = (t >> 4) & 63u;
    unsigned oz  = (t >> 10) & 63u;
    unsigned b   = t >> 16;

    // Exact integer versions of the float32 nearest-index maps (maps are exact in fp32)
    unsigned z = (oz * 9u) >> 2;         // floor(oz * 2.25)
    unsigned y = (oy * 63u) >> 5;        // floor(oy * 1.96875)

    unsigned n  = z / 9u;  unsigned c0 = z - n  * 9u;
    unsigned g1 = y / 9u;  unsigned c1 = y - g1 * 9u;

    const size_t in_base = (size_t)b * (3137u * 768u)
                         + (size_t)(1u + n * 196u + g1 * 14u) * 768u;
    const unsigned chan_base = c0 * 81u + c1 * 9u;

    // float32(768.0/729.0): correctly-rounded, matches JAX weak-float promotion
    const float SC = (float)(768.0 / 729.0);

    float v[4];
    #pragma unroll
    for (int k = 0; k < 4; ++k) {
        unsigned ox = ox0 + (unsigned)k;
        unsigned x  = (ox * 63u) >> 5;               // floor(ox * 1.96875)
        unsigned g2 = x / 9u;
        unsigned c2 = x - g2 * 9u;
        // bit-exact fp32 multiply + floor (values are nonnegative)
        unsigned ch = (unsigned)__float2int_rd((float)(chan_base + c2) * SC);
        v[k] = __ldcs(&in[in_base + (size_t)g2 * 768u + ch]);
    }

    float4 o4 = make_float4(v[0], v[1], v[2], v[3]);
    __stcs(reinterpret_cast<float4*>(out) + t, o4);
}

extern "C" void kernel_launch(void* const* d_in, const int* in_sizes, int n_in,
                              void* d_out, int out_size) {
    const float* in = (const float*)d_in[0];
    float* out = (float*)d_out;
    // out_size = 64 * 64*64*64 = 16,777,216 floats; 4 per thread
    const unsigned n_threads = 16777216u / 4u;    // 4,194,304
    const unsigned block = 256u;
    const unsigned grid = n_threads / block;      // 16,384
    FRAMES_VisionTransformer_28166395527587_kernel<<<grid, block>>>(in, out);
}